// round 5
// baseline (speedup 1.0000x reference)
#include <cuda_runtime.h>
#include <math.h>

#define BB 4
#define NN 4096
#define KK 16
#define NB 32          // 2k neighbors per query
#define TPB 512        // MLP block size (16 warps = 16 queries)
#define FULL 0xffffffffu

typedef unsigned long long u64;

// ---------------- scratch (__device__ globals; no allocation allowed) -------
__device__ float g_feats[BB * NN * NB * 4];                 // {rx,ry,rz,dist} per token, 8MB

// folded params layout inside shared memory:
//  W0 [4][64] (256) | C0 (64) | W1 [64][64] (4096) | C1 (64) | W2 [64][128] (8192) | C2 (128)
#define P_W0 0
#define P_C0 256
#define P_W1 (P_C0 + 64)
#define P_C1 (P_W1 + 4096)
#define P_W2 (P_C1 + 64)
#define P_C2 (P_W2 + 8192)
#define P_TOT (P_C2 + 128)     // 12800 floats

// ---------------- f32x2 helpers --------------------------------------------
__device__ __forceinline__ u64 ffma2(u64 a, u64 b, u64 c) {
    u64 d;
    asm("fma.rn.f32x2 %0, %1, %2, %3;" : "=l"(d) : "l"(a), "l"(b), "l"(c));
    return d;
}
__device__ __forceinline__ u64 pack2(float x) {
    u64 r;
    unsigned xu = __float_as_uint(x);
    asm("mov.b64 %0, {%1, %1};" : "=l"(r) : "r"(xu));
    return r;
}
__device__ __forceinline__ void unpack2(u64 v, float& lo, float& hi) {
    unsigned a, b;
    asm("mov.b64 {%0, %1}, %2;" : "=r"(a), "=r"(b) : "l"(v));
    lo = __uint_as_float(a);
    hi = __uint_as_float(b);
}

// ---------------- kNN: warp per query, warp-collective top-16 --------------
// Lane l holds the l-th best (d2, idx) sorted ascending (lanes 0..15 are the
// real top-16; lanes 16..31 are overflow slots). First 32 candidates are
// initialized by a bitonic warp sort; the rest stream through a warp-uniform
// threshold + ballot, inserting via a branch-free shuffle shift (no divergence).
// grid: (NN/8, B, 2 sets), block 256 (8 warps = 8 queries). dyn smem: 64KB tile.
__global__ __launch_bounds__(256) void knn_kernel(
    const float* __restrict__ p1, const float* __restrict__ p2)
{
    extern __shared__ float4 tile[];       // 4096 x {x,y,z,|r|^2}
    const int lane = threadIdx.x & 31;
    const int warp = threadIdx.x >> 5;
    const int b = blockIdx.y;
    const int set = blockIdx.z;

    const float* qb = p1 + b * 3 * NN;
    const float* rb = (set == 0 ? p1 : p2) + b * 3 * NN;

    for (int j = threadIdx.x; j < NN; j += 256) {
        float rx = rb[j], ry = rb[NN + j], rz = rb[2 * NN + j];
        tile[j] = make_float4(rx, ry, rz, rx * rx + ry * ry + rz * rz);
    }
    __syncthreads();

    const int qi = blockIdx.x * 8 + warp;
    const float qx = qb[qi], qy = qb[NN + qi], qz = qb[2 * NN + qi];
    const float qq = qx * qx + qy * qy + qz * qz;

    // ---- init: bitonic sort of the first 32 candidates across the warp ----
    float ld;
    int   li;
    {
        float4 c = tile[lane];
        float dot = qx * c.x + qy * c.y + qz * c.z;
        ld = fmaf(-2.0f, dot, qq) + c.w;
        li = lane;
#pragma unroll
        for (int k = 2; k <= 32; k <<= 1) {
#pragma unroll
            for (int j = k >> 1; j > 0; j >>= 1) {
                float od = __shfl_xor_sync(FULL, ld, j);
                int   oi = __shfl_xor_sync(FULL, li, j);
                bool up    = ((lane & k) == 0);       // ascending subsequence
                bool lower = ((lane & j) == 0);
                // strict total order via index tie-break -> complementary swaps
                bool lt = (od < ld) || (od == ld && oi < li);
                bool takeOther = (lt == (lower == up));
                ld = takeOther ? od : ld;
                li = takeOther ? oi : li;
            }
        }
    }
    float thresh = __shfl_sync(FULL, ld, 15); // warp-uniform 16th-best distance

    // ---- stream remaining candidates ----
#pragma unroll 2
    for (int t = 1; t < NN / 32; t++) {
        const int j = t * 32 + lane;
        float4 c = tile[j];
        float dot = qx * c.x + qy * c.y + qz * c.z;
        float d2 = fmaf(-2.0f, dot, qq) + c.w;      // same form as reference
        unsigned mask = __ballot_sync(FULL, d2 < thresh);
        if (mask) {
            do {
                int src = __ffs(mask) - 1;
                mask &= mask - 1;
                float xd = __shfl_sync(FULL, d2, src);
                int   xi = __shfl_sync(FULL, j, src);
                float pd = __shfl_up_sync(FULL, ld, 1);
                int   pi = __shfl_up_sync(FULL, li, 1);
                // stale-threshold candidates no-op naturally (take=false everywhere)
                bool take  = (xd < ld);
                bool shift = (lane > 0) && (xd < pd);
                ld = take ? (shift ? pd : xd) : ld;
                li = take ? (shift ? pi : xi) : li;
            } while (mask);
            thresh = __shfl_sync(FULL, ld, 15);
        }
    }

    if (lane < KK) {
        float4 c = tile[li];
        float rx = c.x - qx, ry = c.y - qy, rz = c.z - qz;
        float d2r = rx * rx + ry * ry + rz * rz;
        float dist = sqrtf(fmaxf(d2r, 1e-12f));
        ((float4*)g_feats)[((size_t)(b * NN + qi)) * NB + set * KK + lane] =
            make_float4(rx, ry, rz, dist);
    }
}

// ---------------- fused fold + MLP (f32x2) + max + softmax + weighted sum --
// warp = one query point, lane = one neighbor token.
// BN fold is computed in-block into shared memory (no separate kernel).
#define SMEM_FLOATS (P_TOT + 64 * TPB)
#define SMEM_BYTES  (SMEM_FLOATS * 4)

__global__ __launch_bounds__(TPB) void mlp_kernel(
    const float* __restrict__ p1, float* __restrict__ out,
    const float* __restrict__ w0, const float* __restrict__ b0,
    const float* __restrict__ ga0, const float* __restrict__ be0,
    const float* __restrict__ mm0, const float* __restrict__ vv0,
    const float* __restrict__ w1, const float* __restrict__ b1,
    const float* __restrict__ ga1, const float* __restrict__ be1,
    const float* __restrict__ mm1, const float* __restrict__ vv1,
    const float* __restrict__ w2, const float* __restrict__ b2,
    const float* __restrict__ ga2, const float* __restrict__ be2,
    const float* __restrict__ mm2, const float* __restrict__ vv2)
{
    extern __shared__ float sm[];
    float* sW0  = sm + P_W0;
    float* sW1  = sm + P_W1;
    float* sW2  = sm + P_W2;
    float* sbuf = sm + P_TOT;

    const int tid = threadIdx.x;

    // ---- in-block BN fold: scales into sbuf scratch, then folded weights ----
    {
        float* sc = sbuf;                          // 256 floats of scratch
        if (tid < 64) {
            float s = ga0[tid] / sqrtf(vv0[tid] + 1e-3f);
            sc[tid] = s;
            sm[P_C0 + tid] = (b0[tid] - mm0[tid]) * s + be0[tid];
        } else if (tid < 128) {
            int o = tid - 64;
            float s = ga1[o] / sqrtf(vv1[o] + 1e-3f);
            sc[64 + o] = s;
            sm[P_C1 + o] = (b1[o] - mm1[o]) * s + be1[o];
        } else if (tid < 256) {
            int o = tid - 128;
            float s = ga2[o] / sqrtf(vv2[o] + 1e-3f);
            sc[128 + o] = s;
            sm[P_C2 + o] = (b2[o] - mm2[o]) * s + be2[o];
        }
        __syncthreads();
        for (int i = tid; i < 256; i += TPB) {
            int c = i >> 6, o = i & 63;
            sm[P_W0 + c * 64 + o] = w0[o * 4 + c] * sc[o];
        }
        for (int i = tid; i < 4096; i += TPB) {
            int c = i >> 6, o = i & 63;
            sm[P_W1 + c * 64 + o] = w1[o * 64 + c] * sc[64 + o];
        }
        for (int i = tid; i < 8192; i += TPB) {
            int c = i >> 7, o = i & 127;
            sm[P_W2 + c * 128 + o] = w2[o * 64 + c] * sc[128 + o];
        }
        __syncthreads();
    }

    const int lane = tid & 31;
    const int wg = blockIdx.x * (TPB / 32) + (tid >> 5);   // = b*NN + n
    const int b = wg >> 12;
    const int n = wg & (NN - 1);

    const float4 f = ((const float4*)g_feats)[(size_t)wg * NB + lane];

    u64 acc[32];

    // ---- layer 0: 4 -> 64 ----
    {
        const u64* cb = (const u64*)(sm + P_C0);
#pragma unroll
        for (int p = 0; p < 32; p++) acc[p] = cb[p];
#pragma unroll
        for (int c = 0; c < 4; c++) {
            float xc = (c == 0) ? f.x : (c == 1) ? f.y : (c == 2) ? f.z : f.w;
            u64 xx = pack2(xc);
            const ulonglong2* wp = (const ulonglong2*)(sW0 + c * 64);
#pragma unroll
            for (int q = 0; q < 16; q++) {
                ulonglong2 w = wp[q];
                acc[2 * q + 0] = ffma2(w.x, xx, acc[2 * q + 0]);
                acc[2 * q + 1] = ffma2(w.y, xx, acc[2 * q + 1]);
            }
        }
#pragma unroll
        for (int p = 0; p < 32; p++) {
            float lo, hi; unpack2(acc[p], lo, hi);
            sbuf[(2 * p) * TPB + tid]     = fmaxf(lo, 0.0f);
            sbuf[(2 * p + 1) * TPB + tid] = fmaxf(hi, 0.0f);
        }
    }
    __syncwarp();

    // ---- layer 1: 64 -> 64 ----
    {
        const u64* cb = (const u64*)(sm + P_C1);
#pragma unroll
        for (int p = 0; p < 32; p++) acc[p] = cb[p];
#pragma unroll 2
        for (int c = 0; c < 64; c++) {
            u64 xx = pack2(sbuf[c * TPB + tid]);
            const ulonglong2* wp = (const ulonglong2*)(sW1 + c * 64);
#pragma unroll
            for (int q = 0; q < 16; q++) {
                ulonglong2 w = wp[q];
                acc[2 * q + 0] = ffma2(w.x, xx, acc[2 * q + 0]);
                acc[2 * q + 1] = ffma2(w.y, xx, acc[2 * q + 1]);
            }
        }
#pragma unroll
        for (int p = 0; p < 32; p++) {
            float lo, hi; unpack2(acc[p], lo, hi);
            sbuf[(2 * p) * TPB + tid]     = fmaxf(lo, 0.0f);
            sbuf[(2 * p + 1) * TPB + tid] = fmaxf(hi, 0.0f);
        }
    }
    __syncwarp();

    // ---- layer 2: 64 -> 128 (two halves), fused relu + channel max ----
    float gmax = 0.0f;     // relu floor: max over relu(x) == max(0, max x)
#pragma unroll 1
    for (int h = 0; h < 2; h++) {
        const u64* cb = (const u64*)(sm + P_C2) + h * 32;
#pragma unroll
        for (int p = 0; p < 32; p++) acc[p] = cb[p];
#pragma unroll 2
        for (int c = 0; c < 64; c++) {
            u64 xx = pack2(sbuf[c * TPB + tid]);
            const ulonglong2* wp = (const ulonglong2*)(sW2 + c * 128 + h * 64);
#pragma unroll
            for (int q = 0; q < 16; q++) {
                ulonglong2 w = wp[q];
                acc[2 * q + 0] = ffma2(w.x, xx, acc[2 * q + 0]);
                acc[2 * q + 1] = ffma2(w.y, xx, acc[2 * q + 1]);
            }
        }
#pragma unroll
        for (int p = 0; p < 32; p++) {
            float lo, hi; unpack2(acc[p], lo, hi);
            gmax = fmaxf(gmax, fmaxf(lo, hi));
        }
    }

    // ---- softmax over the 32 neighbors (one warp) ----
    float m = gmax;
#pragma unroll
    for (int off = 16; off; off >>= 1) m = fmaxf(m, __shfl_xor_sync(FULL, m, off));
    float e = __expf(gmax - m);
    float ssum = e;
#pragma unroll
    for (int off = 16; off; off >>= 1) ssum += __shfl_xor_sync(FULL, ssum, off);
    float w = e / ssum;

    // out = sum_j w_j * nn_j = q + sum_j w_j * resi_j   (since sum w = 1)
    float wx = w * f.x, wy = w * f.y, wz = w * f.z;
#pragma unroll
    for (int off = 16; off; off >>= 1) {
        wx += __shfl_xor_sync(FULL, wx, off);
        wy += __shfl_xor_sync(FULL, wy, off);
        wz += __shfl_xor_sync(FULL, wz, off);
    }
    if (lane == 0) {
        const float* qb = p1 + b * 3 * NN;
        out[b * 3 * NN + n]          = qb[n]          + wx;
        out[b * 3 * NN + NN + n]     = qb[NN + n]     + wy;
        out[b * 3 * NN + 2 * NN + n] = qb[2 * NN + n] + wz;
    }
}

// ---------------- launch ---------------------------------------------------
extern "C" void kernel_launch(void* const* d_in, const int* in_sizes, int n_in,
                              void* d_out, int out_size)
{
    const float* p1 = (const float*)d_in[0];
    const float* p2 = (const float*)d_in[1];
    // d_in[2] = k (fixed at 16 for this shape)
    const float* w0 = (const float*)d_in[3];
    const float* b0 = (const float*)d_in[4];
    const float* g0 = (const float*)d_in[5];
    const float* e0 = (const float*)d_in[6];
    const float* m0 = (const float*)d_in[7];
    const float* v0 = (const float*)d_in[8];
    const float* w1 = (const float*)d_in[9];
    const float* b1 = (const float*)d_in[10];
    const float* g1 = (const float*)d_in[11];
    const float* e1 = (const float*)d_in[12];
    const float* m1 = (const float*)d_in[13];
    const float* v1 = (const float*)d_in[14];
    const float* w2 = (const float*)d_in[15];
    const float* b2 = (const float*)d_in[16];
    const float* g2 = (const float*)d_in[17];
    const float* e2 = (const float*)d_in[18];
    const float* m2 = (const float*)d_in[19];
    const float* v2 = (const float*)d_in[20];

    cudaFuncSetAttribute(mlp_kernel, cudaFuncAttributeMaxDynamicSharedMemorySize, SMEM_BYTES);
    cudaFuncSetAttribute(knn_kernel, cudaFuncAttributeMaxDynamicSharedMemorySize, NN * 16);

    knn_kernel<<<dim3(NN / 8, BB, 2), 256, NN * 16>>>(p1, p2);

    const int nwarps = BB * NN;                 // 16384 queries
    mlp_kernel<<<nwarps / (TPB / 32), TPB, SMEM_BYTES>>>(
        p1, (float*)d_out,
        w0, b0, g0, e0, m0, v0,
        w1, b1, g1, e1, m1, v1,
        w2, b2, g2, e2, m2, v2);
}

// round 7
// speedup vs baseline: 1.3478x; 1.3478x over previous
#include <cuda_runtime.h>
#include <math.h>

#define BB 4
#define NN 4096
#define KK 16
#define NB 32          // 2k neighbors per query
#define TPB 512        // MLP block size (512 tokens = 16 queries)
#define FULL 0xffffffffu

typedef unsigned long long u64;

// ---------------- scratch (__device__ globals; no allocation allowed) -------
__device__ float g_feats[BB * NN * NB * 4];                 // {rx,ry,rz,dist} per token, 8MB

// folded params layout inside shared memory:
//  W0 [4][64] (256) | C0 (64) | W1 [64][64] (4096) | C1 (64) | W2 [64][128] (8192) | C2 (128)
#define P_W0 0
#define P_C0 256
#define P_W1 (P_C0 + 64)
#define P_C1 (P_W1 + 4096)
#define P_W2 (P_C1 + 64)
#define P_C2 (P_W2 + 8192)
#define P_TOT (P_C2 + 128)     // 12800 floats

// ---------------- f32x2 helpers --------------------------------------------
__device__ __forceinline__ u64 ffma2(u64 a, u64 b, u64 c) {
    u64 d;
    asm("fma.rn.f32x2 %0, %1, %2, %3;" : "=l"(d) : "l"(a), "l"(b), "l"(c));
    return d;
}
__device__ __forceinline__ u64 pack2(float x) {
    u64 r;
    unsigned xu = __float_as_uint(x);
    asm("mov.b64 %0, {%1, %1};" : "=l"(r) : "r"(xu));
    return r;
}
__device__ __forceinline__ void unpack2(u64 v, float& lo, float& hi) {
    unsigned a, b;
    asm("mov.b64 {%0, %1}, %2;" : "=r"(a), "=r"(b) : "l"(v));
    lo = __uint_as_float(a);
    hi = __uint_as_float(b);
}

// ---------------- kNN: warp per query, warp-collective top-16 --------------
// (unchanged from last passing round)
__global__ __launch_bounds__(256) void knn_kernel(
    const float* __restrict__ p1, const float* __restrict__ p2)
{
    extern __shared__ float4 tile[];       // 4096 x {x,y,z,|r|^2}
    const int lane = threadIdx.x & 31;
    const int warp = threadIdx.x >> 5;
    const int b = blockIdx.y;
    const int set = blockIdx.z;

    const float* qb = p1 + b * 3 * NN;
    const float* rb = (set == 0 ? p1 : p2) + b * 3 * NN;

    for (int j = threadIdx.x; j < NN; j += 256) {
        float rx = rb[j], ry = rb[NN + j], rz = rb[2 * NN + j];
        tile[j] = make_float4(rx, ry, rz, rx * rx + ry * ry + rz * rz);
    }
    __syncthreads();

    const int qi = blockIdx.x * 8 + warp;
    const float qx = qb[qi], qy = qb[NN + qi], qz = qb[2 * NN + qi];
    const float qq = qx * qx + qy * qy + qz * qz;

    // ---- init: bitonic sort of the first 32 candidates across the warp ----
    float ld;
    int   li;
    {
        float4 c = tile[lane];
        float dot = qx * c.x + qy * c.y + qz * c.z;
        ld = fmaf(-2.0f, dot, qq) + c.w;
        li = lane;
#pragma unroll
        for (int k = 2; k <= 32; k <<= 1) {
#pragma unroll
            for (int j = k >> 1; j > 0; j >>= 1) {
                float od = __shfl_xor_sync(FULL, ld, j);
                int   oi = __shfl_xor_sync(FULL, li, j);
                bool up    = ((lane & k) == 0);
                bool lower = ((lane & j) == 0);
                bool lt = (od < ld) || (od == ld && oi < li);
                bool takeOther = (lt == (lower == up));
                ld = takeOther ? od : ld;
                li = takeOther ? oi : li;
            }
        }
    }
    float thresh = __shfl_sync(FULL, ld, 15);

    // ---- stream remaining candidates ----
#pragma unroll 2
    for (int t = 1; t < NN / 32; t++) {
        const int j = t * 32 + lane;
        float4 c = tile[j];
        float dot = qx * c.x + qy * c.y + qz * c.z;
        float d2 = fmaf(-2.0f, dot, qq) + c.w;
        unsigned mask = __ballot_sync(FULL, d2 < thresh);
        if (mask) {
            do {
                int src = __ffs(mask) - 1;
                mask &= mask - 1;
                float xd = __shfl_sync(FULL, d2, src);
                int   xi = __shfl_sync(FULL, j, src);
                float pd = __shfl_up_sync(FULL, ld, 1);
                int   pi = __shfl_up_sync(FULL, li, 1);
                bool take  = (xd < ld);
                bool shift = (lane > 0) && (xd < pd);
                ld = take ? (shift ? pd : xd) : ld;
                li = take ? (shift ? pi : xi) : li;
            } while (mask);
            thresh = __shfl_sync(FULL, ld, 15);
        }
    }

    if (lane < KK) {
        float4 c = tile[li];
        float rx = c.x - qx, ry = c.y - qy, rz = c.z - qz;
        float d2r = rx * rx + ry * ry + rz * rz;
        float dist = sqrtf(fmaxf(d2r, 1e-12f));
        ((float4*)g_feats)[((size_t)(b * NN + qi)) * NB + set * KK + lane] =
            make_float4(rx, ry, rz, dist);
    }
}

// ---------------- fused fold + MLP + max + softmax + weighted sum ----------
// Register-blocked GEMM: thread = 16 output channels x 4 consecutive tokens.
//   grp = tid & 127 -> tokens 4*grp..4*grp+3 ; g = tid >> 7 -> channels 16g..16g+15
// Activations live in smem as [channel][512 tokens] (16B-stride, conflict-free).
// Accumulators: f32x2 channel pairs, 8 per token x 4 tokens = 32 u64.
#define SMEM_FLOATS (P_TOT + 64 * TPB + 4 * TPB)
#define SMEM_BYTES  (SMEM_FLOATS * 4)

__global__ __launch_bounds__(TPB) void mlp_kernel(
    const float* __restrict__ p1, float* __restrict__ out,
    const float* __restrict__ w0, const float* __restrict__ b0,
    const float* __restrict__ ga0, const float* __restrict__ be0,
    const float* __restrict__ mm0, const float* __restrict__ vv0,
    const float* __restrict__ w1, const float* __restrict__ b1,
    const float* __restrict__ ga1, const float* __restrict__ be1,
    const float* __restrict__ mm1, const float* __restrict__ vv1,
    const float* __restrict__ w2, const float* __restrict__ b2,
    const float* __restrict__ ga2, const float* __restrict__ be2,
    const float* __restrict__ mm2, const float* __restrict__ vv2)
{
    extern __shared__ float sm[];
    float* sAct = sm + P_TOT;              // [64][TPB]
    float* sAux = sAct + 64 * TPB;         // [4][TPB]  feats in / max-reduce later

    const int tid = threadIdx.x;

    // ---- in-block BN fold (scratch = first 256 floats of sAct) ----
    {
        float* sc = sAct;
        if (tid < 64) {
            float s = ga0[tid] / sqrtf(vv0[tid] + 1e-3f);
            sc[tid] = s;
            sm[P_C0 + tid] = (b0[tid] - mm0[tid]) * s + be0[tid];
        } else if (tid < 128) {
            int o = tid - 64;
            float s = ga1[o] / sqrtf(vv1[o] + 1e-3f);
            sc[64 + o] = s;
            sm[P_C1 + o] = (b1[o] - mm1[o]) * s + be1[o];
        } else if (tid < 256) {
            int o = tid - 128;
            float s = ga2[o] / sqrtf(vv2[o] + 1e-3f);
            sc[128 + o] = s;
            sm[P_C2 + o] = (b2[o] - mm2[o]) * s + be2[o];
        }
        __syncthreads();
        for (int i = tid; i < 256; i += TPB) {
            int c = i >> 6, o = i & 63;
            sm[P_W0 + c * 64 + o] = w0[o * 4 + c] * sc[o];
        }
        for (int i = tid; i < 4096; i += TPB) {
            int c = i >> 6, o = i & 63;
            sm[P_W1 + c * 64 + o] = w1[o * 64 + c] * sc[64 + o];
        }
        for (int i = tid; i < 8192; i += TPB) {
            int c = i >> 7, o = i & 127;
            sm[P_W2 + c * 128 + o] = w2[o * 64 + c] * sc[128 + o];
        }
        __syncthreads();
    }

    // ---- phase A: load my token's feats, publish as layer-0 activations ----
    const int lane = tid & 31;
    const int wg = blockIdx.x * (TPB / 32) + (tid >> 5);   // = b*NN + n
    const int b = wg >> 12;
    const int n = wg & (NN - 1);
    const float4 f = ((const float4*)g_feats)[(size_t)wg * NB + lane];
    sAux[0 * TPB + tid] = f.x;
    sAux[1 * TPB + tid] = f.y;
    sAux[2 * TPB + tid] = f.z;
    sAux[3 * TPB + tid] = f.w;
    __syncthreads();

    const int grp = tid & 127;          // token group (4 tokens)
    const int g   = tid >> 7;           // channel group (16 channels)
    const int gb  = g * 16;

    u64 acc[32];                        // acc[t*8+p] = channels (gb+2p, gb+2p+1), token t

    // ================= layer 0: 4 -> 64 =================
    {
        const u64* cb = (const u64*)(sm + P_C0) + g * 8;
#pragma unroll
        for (int t = 0; t < 4; t++)
#pragma unroll
            for (int p = 0; p < 8; p++) acc[t * 8 + p] = cb[p];
#pragma unroll
        for (int c = 0; c < 4; c++) {
            float4 a = *(const float4*)(sAux + c * TPB + grp * 4);
            u64 a0 = pack2(a.x), a1 = pack2(a.y), a2 = pack2(a.z), a3 = pack2(a.w);
            const ulonglong2* wp = (const ulonglong2*)(sm + P_W0 + c * 64 + gb);
            ulonglong2 wA = wp[0], wB = wp[1], wC = wp[2], wD = wp[3];
            u64 wv[8] = {wA.x, wA.y, wB.x, wB.y, wC.x, wC.y, wD.x, wD.y};
#pragma unroll
            for (int p = 0; p < 8; p++) {
                acc[0 * 8 + p] = ffma2(wv[p], a0, acc[0 * 8 + p]);
                acc[1 * 8 + p] = ffma2(wv[p], a1, acc[1 * 8 + p]);
                acc[2 * 8 + p] = ffma2(wv[p], a2, acc[2 * 8 + p]);
                acc[3 * 8 + p] = ffma2(wv[p], a3, acc[3 * 8 + p]);
            }
        }
        __syncthreads();   // all layer-0 reads of sAux done; safe to write sAct
#pragma unroll
        for (int p = 0; p < 8; p++) {
            float x0, y0, x1, y1, x2, y2, x3, y3;
            unpack2(acc[0 * 8 + p], x0, y0);
            unpack2(acc[1 * 8 + p], x1, y1);
            unpack2(acc[2 * 8 + p], x2, y2);
            unpack2(acc[3 * 8 + p], x3, y3);
            float4 lo = make_float4(fmaxf(x0, 0.f), fmaxf(x1, 0.f), fmaxf(x2, 0.f), fmaxf(x3, 0.f));
            float4 hi = make_float4(fmaxf(y0, 0.f), fmaxf(y1, 0.f), fmaxf(y2, 0.f), fmaxf(y3, 0.f));
            *(float4*)(sAct + (gb + 2 * p)     * TPB + grp * 4) = lo;
            *(float4*)(sAct + (gb + 2 * p + 1) * TPB + grp * 4) = hi;
        }
        __syncthreads();
    }

    // ================= layer 1: 64 -> 64 (in place) =================
    {
        const u64* cb = (const u64*)(sm + P_C1) + g * 8;
#pragma unroll
        for (int t = 0; t < 4; t++)
#pragma unroll
            for (int p = 0; p < 8; p++) acc[t * 8 + p] = cb[p];
#pragma unroll 2
        for (int c = 0; c < 64; c++) {
            float4 a = *(const float4*)(sAct + c * TPB + grp * 4);
            u64 a0 = pack2(a.x), a1 = pack2(a.y), a2 = pack2(a.z), a3 = pack2(a.w);
            const ulonglong2* wp = (const ulonglong2*)(sm + P_W1 + c * 64 + gb);
            ulonglong2 wA = wp[0], wB = wp[1], wC = wp[2], wD = wp[3];
            u64 wv[8] = {wA.x, wA.y, wB.x, wB.y, wC.x, wC.y, wD.x, wD.y};
#pragma unroll
            for (int p = 0; p < 8; p++) {
                acc[0 * 8 + p] = ffma2(wv[p], a0, acc[0 * 8 + p]);
                acc[1 * 8 + p] = ffma2(wv[p], a1, acc[1 * 8 + p]);
                acc[2 * 8 + p] = ffma2(wv[p], a2, acc[2 * 8 + p]);
                acc[3 * 8 + p] = ffma2(wv[p], a3, acc[3 * 8 + p]);
            }
        }
        __syncthreads();   // all reads done before in-place overwrite
#pragma unroll
        for (int p = 0; p < 8; p++) {
            float x0, y0, x1, y1, x2, y2, x3, y3;
            unpack2(acc[0 * 8 + p], x0, y0);
            unpack2(acc[1 * 8 + p], x1, y1);
            unpack2(acc[2 * 8 + p], x2, y2);
            unpack2(acc[3 * 8 + p], x3, y3);
            float4 lo = make_float4(fmaxf(x0, 0.f), fmaxf(x1, 0.f), fmaxf(x2, 0.f), fmaxf(x3, 0.f));
            float4 hi = make_float4(fmaxf(y0, 0.f), fmaxf(y1, 0.f), fmaxf(y2, 0.f), fmaxf(y3, 0.f));
            *(float4*)(sAct + (gb + 2 * p)     * TPB + grp * 4) = lo;
            *(float4*)(sAct + (gb + 2 * p + 1) * TPB + grp * 4) = hi;
        }
        __syncthreads();
    }

    // ================= layer 2: 64 -> 128, fused channel max =================
    float tmax0 = 0.f, tmax1 = 0.f, tmax2 = 0.f, tmax3 = 0.f;  // relu floor
#pragma unroll 1
    for (int h = 0; h < 2; h++) {
        const u64* cb = (const u64*)(sm + P_C2) + h * 32 + g * 8;
#pragma unroll
        for (int t = 0; t < 4; t++)
#pragma unroll
            for (int p = 0; p < 8; p++) acc[t * 8 + p] = cb[p];
#pragma unroll 2
        for (int c = 0; c < 64; c++) {
            float4 a = *(const float4*)(sAct + c * TPB + grp * 4);
            u64 a0 = pack2(a.x), a1 = pack2(a.y), a2 = pack2(a.z), a3 = pack2(a.w);
            const ulonglong2* wp = (const ulonglong2*)(sm + P_W2 + c * 128 + h * 64 + gb);
            ulonglong2 wA = wp[0], wB = wp[1], wC = wp[2], wD = wp[3];
            u64 wv[8] = {wA.x, wA.y, wB.x, wB.y, wC.x, wC.y, wD.x, wD.y};
#pragma unroll
            for (int p = 0; p < 8; p++) {
                acc[0 * 8 + p] = ffma2(wv[p], a0, acc[0 * 8 + p]);
                acc[1 * 8 + p] = ffma2(wv[p], a1, acc[1 * 8 + p]);
                acc[2 * 8 + p] = ffma2(wv[p], a2, acc[2 * 8 + p]);
                acc[3 * 8 + p] = ffma2(wv[p], a3, acc[3 * 8 + p]);
            }
        }
#pragma unroll
        for (int p = 0; p < 8; p++) {
            float lo, hi;
            unpack2(acc[0 * 8 + p], lo, hi); tmax0 = fmaxf(tmax0, fmaxf(lo, hi));
            unpack2(acc[1 * 8 + p], lo, hi); tmax1 = fmaxf(tmax1, fmaxf(lo, hi));
            unpack2(acc[2 * 8 + p], lo, hi); tmax2 = fmaxf(tmax2, fmaxf(lo, hi));
            unpack2(acc[3 * 8 + p], lo, hi); tmax3 = fmaxf(tmax3, fmaxf(lo, hi));
        }
    }
    __syncthreads();    // sAux free for reuse as partial-max buffer
    sAux[g * TPB + grp * 4 + 0] = tmax0;
    sAux[g * TPB + grp * 4 + 1] = tmax1;
    sAux[g * TPB + grp * 4 + 2] = tmax2;
    sAux[g * TPB + grp * 4 + 3] = tmax3;
    __syncthreads();

    // ---- back to thread = token: combine 4 channel-group partials ----
    float gmax = fmaxf(fmaxf(sAux[tid], sAux[TPB + tid]),
                       fmaxf(sAux[2 * TPB + tid], sAux[3 * TPB + tid]));

    // ---- softmax over the 32 neighbors (one warp = one query) ----
    float m = gmax;
#pragma unroll
    for (int off = 16; off; off >>= 1) m = fmaxf(m, __shfl_xor_sync(FULL, m, off));
    float e = __expf(gmax - m);
    float ssum = e;
#pragma unroll
    for (int off = 16; off; off >>= 1) ssum += __shfl_xor_sync(FULL, ssum, off);
    float w = e / ssum;

    // out = q + sum_j w_j * resi_j   (since sum w = 1)
    float wx = w * f.x, wy = w * f.y, wz = w * f.z;
#pragma unroll
    for (int off = 16; off; off >>= 1) {
        wx += __shfl_xor_sync(FULL, wx, off);
        wy += __shfl_xor_sync(FULL, wy, off);
        wz += __shfl_xor_sync(FULL, wz, off);
    }
    if (lane == 0) {
        const float* qb = p1 + b * 3 * NN;
        out[b * 3 * NN + n]          = qb[n]          + wx;
        out[b * 3 * NN + NN + n]     = qb[NN + n]     + wy;
        out[b * 3 * NN + 2 * NN + n] = qb[2 * NN + n] + wz;
    }
}

// ---------------- launch ---------------------------------------------------
extern "C" void kernel_launch(void* const* d_in, const int* in_sizes, int n_in,
                              void* d_out, int out_size)
{
    const float* p1 = (const float*)d_in[0];
    const float* p2 = (const float*)d_in[1];
    // d_in[2] = k (fixed at 16 for this shape)
    const float* w0 = (const float*)d_in[3];
    const float* b0 = (const float*)d_in[4];
    const float* g0 = (const float*)d_in[5];
    const float* e0 = (const float*)d_in[6];
    const float* m0 = (const float*)d_in[7];
    const float* v0 = (const float*)d_in[8];
    const float* w1 = (const float*)d_in[9];
    const float* b1 = (const float*)d_in[10];
    const float* g1 = (const float*)d_in[11];
    const float* e1 = (const float*)d_in[12];
    const float* m1 = (const float*)d_in[13];
    const float* v1 = (const float*)d_in[14];
    const float* w2 = (const float*)d_in[15];
    const float* b2 = (const float*)d_in[16];
    const float* g2 = (const float*)d_in[17];
    const float* e2 = (const float*)d_in[18];
    const float* m2 = (const float*)d_in[19];
    const float* v2 = (const float*)d_in[20];

    cudaFuncSetAttribute(mlp_kernel, cudaFuncAttributeMaxDynamicSharedMemorySize, SMEM_BYTES);
    cudaFuncSetAttribute(knn_kernel, cudaFuncAttributeMaxDynamicSharedMemorySize, NN * 16);

    knn_kernel<<<dim3(NN / 8, BB, 2), 256, NN * 16>>>(p1, p2);

    const int nwarps = BB * NN;                 // 16384 queries
    mlp_kernel<<<nwarps / (TPB / 32), TPB, SMEM_BYTES>>>(
        p1, (float*)d_out,
        w0, b0, g0, e0, m0, v0,
        w1, b1, g1, e1, m1, v1,
        w2, b2, g2, e2, m2, v2);
}

// round 8
// speedup vs baseline: 1.3702x; 1.0166x over previous
#include <cuda_runtime.h>
#include <math.h>

#define BB 4
#define NN 4096
#define KK 16
#define NB 32          // 2k neighbors per query
#define FULL 0xffffffffu

typedef unsigned long long u64;

// ---------------- scratch (__device__ globals; no allocation allowed) -------
__device__ float g_feats[BB * NN * NB * 4];                 // {rx,ry,rz,dist} per token, 8MB

// ---------------- f32x2 helpers --------------------------------------------
__device__ __forceinline__ u64 ffma2(u64 a, u64 b, u64 c) {
    u64 d;
    asm("fma.rn.f32x2 %0, %1, %2, %3;" : "=l"(d) : "l"(a), "l"(b), "l"(c));
    return d;
}
__device__ __forceinline__ u64 pack2(float x) {
    u64 r;
    unsigned xu = __float_as_uint(x);
    asm("mov.b64 %0, {%1, %1};" : "=l"(r) : "r"(xu));
    return r;
}
__device__ __forceinline__ void unpack2(u64 v, float& lo, float& hi) {
    unsigned a, b;
    asm("mov.b64 {%0, %1}, %2;" : "=r"(a), "=r"(b) : "l"(v));
    lo = __uint_as_float(a);
    hi = __uint_as_float(b);
}

// ---------------- kNN: warp per query, warp-collective top-16 --------------
// 512 threads = 16 queries per block -> tile load amortized over 2x queries.
// grid: (NN/16, B, 2 sets). dyn smem: 64KB tile -> 3 CTAs/SM.
__global__ __launch_bounds__(512) void knn_kernel(
    const float* __restrict__ p1, const float* __restrict__ p2)
{
    extern __shared__ float4 tile[];       // 4096 x {x,y,z,|r|^2}
    const int lane = threadIdx.x & 31;
    const int warp = threadIdx.x >> 5;
    const int b = blockIdx.y;
    const int set = blockIdx.z;

    const float* qb = p1 + b * 3 * NN;
    const float* rb = (set == 0 ? p1 : p2) + b * 3 * NN;

    for (int j = threadIdx.x; j < NN; j += 512) {
        float rx = rb[j], ry = rb[NN + j], rz = rb[2 * NN + j];
        tile[j] = make_float4(rx, ry, rz, rx * rx + ry * ry + rz * rz);
    }
    __syncthreads();

    const int qi = blockIdx.x * 16 + warp;
    const float qx = qb[qi], qy = qb[NN + qi], qz = qb[2 * NN + qi];
    const float qq = qx * qx + qy * qy + qz * qz;

    // ---- init: bitonic sort of the first 32 candidates across the warp ----
    float ld;
    int   li;
    {
        float4 c = tile[lane];
        float dot = qx * c.x + qy * c.y + qz * c.z;
        ld = fmaf(-2.0f, dot, qq) + c.w;
        li = lane;
#pragma unroll
        for (int k = 2; k <= 32; k <<= 1) {
#pragma unroll
            for (int j = k >> 1; j > 0; j >>= 1) {
                float od = __shfl_xor_sync(FULL, ld, j);
                int   oi = __shfl_xor_sync(FULL, li, j);
                bool up    = ((lane & k) == 0);
                bool lower = ((lane & j) == 0);
                bool lt = (od < ld) || (od == ld && oi < li);
                bool takeOther = (lt == (lower == up));
                ld = takeOther ? od : ld;
                li = takeOther ? oi : li;
            }
        }
    }
    float thresh = __shfl_sync(FULL, ld, 15);

    // ---- stream remaining candidates ----
#pragma unroll 2
    for (int t = 1; t < NN / 32; t++) {
        const int j = t * 32 + lane;
        float4 c = tile[j];
        float dot = qx * c.x + qy * c.y + qz * c.z;
        float d2 = fmaf(-2.0f, dot, qq) + c.w;
        unsigned mask = __ballot_sync(FULL, d2 < thresh);
        if (mask) {
            do {
                int src = __ffs(mask) - 1;
                mask &= mask - 1;
                float xd = __shfl_sync(FULL, d2, src);
                int   xi = __shfl_sync(FULL, j, src);
                float pd = __shfl_up_sync(FULL, ld, 1);
                int   pi = __shfl_up_sync(FULL, li, 1);
                bool take  = (xd < ld);
                bool shift = (lane > 0) && (xd < pd);
                ld = take ? (shift ? pd : xd) : ld;
                li = take ? (shift ? pi : xi) : li;
            } while (mask);
            thresh = __shfl_sync(FULL, ld, 15);
        }
    }

    if (lane < KK) {
        float4 c = tile[li];
        float rx = c.x - qx, ry = c.y - qy, rz = c.z - qz;
        float d2r = rx * rx + ry * ry + rz * rz;
        float dist = sqrtf(fmaxf(d2r, 1e-12f));
        ((float4*)g_feats)[((size_t)(b * NN + qi)) * NB + set * KK + lane] =
            make_float4(rx, ry, rz, dist);
    }
}

// ---------------- fused fold + MLP + max + softmax + weighted sum ----------
// 256-token / 256-thread blocks, 2 CTAs/SM.
// Thread = 16 output channels x 4 tokens: grp = tid & 63, g = tid >> 6.
// Smem: small params + two 4096-float weight slabs (WA holds W1, later W2[h=1];
// WB holds W2[h=0]) + act[64][256]. Max-reduce aliases act. ~98KB total.
#define MT 256                      // tokens (= threads) per MLP block
#define S_W0  0
#define S_C0  256
#define S_C1  320
#define S_C2  384                   // 128 entries
#define S_SC2 512                   // 64 scales for out-ch 64..127 (refold)
#define S_WA  576                   // W1, then W2 h=1
#define S_WB  (S_WA + 4096)         // W2 h=0
#define S_ACT (S_WB + 4096)         // [64][MT]
#define SMEM_FLOATS (S_ACT + 64 * MT)
#define SMEM_BYTES  (SMEM_FLOATS * 4)

__global__ __launch_bounds__(MT) void mlp_kernel(
    const float* __restrict__ p1, float* __restrict__ out,
    const float* __restrict__ w0, const float* __restrict__ b0,
    const float* __restrict__ ga0, const float* __restrict__ be0,
    const float* __restrict__ mm0, const float* __restrict__ vv0,
    const float* __restrict__ w1, const float* __restrict__ b1,
    const float* __restrict__ ga1, const float* __restrict__ be1,
    const float* __restrict__ mm1, const float* __restrict__ vv1,
    const float* __restrict__ w2, const float* __restrict__ b2,
    const float* __restrict__ ga2, const float* __restrict__ be2,
    const float* __restrict__ mm2, const float* __restrict__ vv2)
{
    extern __shared__ float sm[];
    float* sAct = sm + S_ACT;

    const int tid = threadIdx.x;

    // ---- in-block BN fold (scales recomputed per element; no scratch) ----
    if (tid < 64) {
        float s = ga0[tid] * rsqrtf(vv0[tid] + 1e-3f);
        sm[S_C0 + tid] = (b0[tid] - mm0[tid]) * s + be0[tid];
    } else if (tid < 128) {
        int o = tid - 64;
        float s = ga1[o] * rsqrtf(vv1[o] + 1e-3f);
        sm[S_C1 + o] = (b1[o] - mm1[o]) * s + be1[o];
    } else {
        int o = tid - 128;
        float s = ga2[o] * rsqrtf(vv2[o] + 1e-3f);
        sm[S_C2 + o] = (b2[o] - mm2[o]) * s + be2[o];
        if (o >= 64) sm[S_SC2 + o - 64] = s;
    }
    // W0 [4][64]
    {
        int c = tid >> 6, o = tid & 63;
        float s = ga0[o] * rsqrtf(vv0[o] + 1e-3f);
        sm[S_W0 + c * 64 + o] = w0[o * 4 + c] * s;
    }
    // W1 [64c][64o] -> WA
    for (int i = tid; i < 4096; i += MT) {
        int c = i >> 6, o = i & 63;
        float s = ga1[o] * rsqrtf(vv1[o] + 1e-3f);
        sm[S_WA + i] = w1[o * 64 + c] * s;
    }
    // W2 h=0 [64c][64o] -> WB
    for (int i = tid; i < 4096; i += MT) {
        int c = i >> 6, o = i & 63;
        float s = ga2[o] * rsqrtf(vv2[o] + 1e-3f);
        sm[S_WB + i] = w2[o * 64 + c] * s;
    }
    __syncthreads();

    const int grp = tid & 63;           // token group (4 tokens)
    const int g   = tid >> 6;           // channel group (16 channels)
    const int gb  = g * 16;
    const size_t tokBase = (size_t)blockIdx.x * MT;

    u64 acc[32];                        // acc[t*8+p] = ch (gb+2p, gb+2p+1), token t

    // ================= layer 0: 4 -> 64 (feats straight from gmem) =========
    {
        float4 ft[4];
#pragma unroll
        for (int t = 0; t < 4; t++)
            ft[t] = ((const float4*)g_feats)[tokBase + grp * 4 + t];

        const u64* cb = (const u64*)(sm + S_C0) + g * 8;
#pragma unroll
        for (int t = 0; t < 4; t++)
#pragma unroll
            for (int p = 0; p < 8; p++) acc[t * 8 + p] = cb[p];
#pragma unroll
        for (int c = 0; c < 4; c++) {
            float v0 = (c == 0) ? ft[0].x : (c == 1) ? ft[0].y : (c == 2) ? ft[0].z : ft[0].w;
            float v1 = (c == 0) ? ft[1].x : (c == 1) ? ft[1].y : (c == 2) ? ft[1].z : ft[1].w;
            float v2 = (c == 0) ? ft[2].x : (c == 1) ? ft[2].y : (c == 2) ? ft[2].z : ft[2].w;
            float v3 = (c == 0) ? ft[3].x : (c == 1) ? ft[3].y : (c == 2) ? ft[3].z : ft[3].w;
            u64 a0 = pack2(v0), a1 = pack2(v1), a2 = pack2(v2), a3 = pack2(v3);
            const ulonglong2* wp = (const ulonglong2*)(sm + S_W0 + c * 64 + gb);
            ulonglong2 wA = wp[0], wB = wp[1], wC = wp[2], wD = wp[3];
            u64 wv[8] = {wA.x, wA.y, wB.x, wB.y, wC.x, wC.y, wD.x, wD.y};
#pragma unroll
            for (int p = 0; p < 8; p++) {
                acc[0 * 8 + p] = ffma2(wv[p], a0, acc[0 * 8 + p]);
                acc[1 * 8 + p] = ffma2(wv[p], a1, acc[1 * 8 + p]);
                acc[2 * 8 + p] = ffma2(wv[p], a2, acc[2 * 8 + p]);
                acc[3 * 8 + p] = ffma2(wv[p], a3, acc[3 * 8 + p]);
            }
        }
#pragma unroll
        for (int p = 0; p < 8; p++) {
            float x0, y0, x1, y1, x2, y2, x3, y3;
            unpack2(acc[0 * 8 + p], x0, y0);
            unpack2(acc[1 * 8 + p], x1, y1);
            unpack2(acc[2 * 8 + p], x2, y2);
            unpack2(acc[3 * 8 + p], x3, y3);
            float4 lo = make_float4(fmaxf(x0, 0.f), fmaxf(x1, 0.f), fmaxf(x2, 0.f), fmaxf(x3, 0.f));
            float4 hi = make_float4(fmaxf(y0, 0.f), fmaxf(y1, 0.f), fmaxf(y2, 0.f), fmaxf(y3, 0.f));
            *(float4*)(sAct + (gb + 2 * p)     * MT + grp * 4) = lo;
            *(float4*)(sAct + (gb + 2 * p + 1) * MT + grp * 4) = hi;
        }
        __syncthreads();
    }

    // ================= layer 1: 64 -> 64 =================
    {
        const u64* cb = (const u64*)(sm + S_C1) + g * 8;
#pragma unroll
        for (int t = 0; t < 4; t++)
#pragma unroll
            for (int p = 0; p < 8; p++) acc[t * 8 + p] = cb[p];
#pragma unroll 2
        for (int c = 0; c < 64; c++) {
            float4 a = *(const float4*)(sAct + c * MT + grp * 4);
            u64 a0 = pack2(a.x), a1 = pack2(a.y), a2 = pack2(a.z), a3 = pack2(a.w);
            const ulonglong2* wp = (const ulonglong2*)(sm + S_WA + c * 64 + gb);
            ulonglong2 wA = wp[0], wB = wp[1], wC = wp[2], wD = wp[3];
            u64 wv[8] = {wA.x, wA.y, wB.x, wB.y, wC.x, wC.y, wD.x, wD.y};
#pragma unroll
            for (int p = 0; p < 8; p++) {
                acc[0 * 8 + p] = ffma2(wv[p], a0, acc[0 * 8 + p]);
                acc[1 * 8 + p] = ffma2(wv[p], a1, acc[1 * 8 + p]);
                acc[2 * 8 + p] = ffma2(wv[p], a2, acc[2 * 8 + p]);
                acc[3 * 8 + p] = ffma2(wv[p], a3, acc[3 * 8 + p]);
            }
        }
        __syncthreads();   // all layer-1 reads (act + WA) done
#pragma unroll
        for (int p = 0; p < 8; p++) {
            float x0, y0, x1, y1, x2, y2, x3, y3;
            unpack2(acc[0 * 8 + p], x0, y0);
            unpack2(acc[1 * 8 + p], x1, y1);
            unpack2(acc[2 * 8 + p], x2, y2);
            unpack2(acc[3 * 8 + p], x3, y3);
            float4 lo = make_float4(fmaxf(x0, 0.f), fmaxf(x1, 0.f), fmaxf(x2, 0.f), fmaxf(x3, 0.f));
            float4 hi = make_float4(fmaxf(y0, 0.f), fmaxf(y1, 0.f), fmaxf(y2, 0.f), fmaxf(y3, 0.f));
            *(float4*)(sAct + (gb + 2 * p)     * MT + grp * 4) = lo;
            *(float4*)(sAct + (gb + 2 * p + 1) * MT + grp * 4) = hi;
        }
        // refold WA <- W2 h=1 (W1 is dead now)
        for (int i = tid; i < 4096; i += MT) {
            int c = i >> 6, o = i & 63;
            sm[S_WA + i] = w2[(o + 64) * 64 + c] * sm[S_SC2 + o];
        }
        __syncthreads();
    }

    // ================= layer 2: 64 -> 128 (h0 from WB, h1 from WA) =========
    float tmax0 = 0.f, tmax1 = 0.f, tmax2 = 0.f, tmax3 = 0.f;  // relu floor
#pragma unroll 1
    for (int h = 0; h < 2; h++) {
        const float* wbase = sm + (h == 0 ? S_WB : S_WA);
        const u64* cb = (const u64*)(sm + S_C2) + h * 32 + g * 8;
#pragma unroll
        for (int t = 0; t < 4; t++)
#pragma unroll
            for (int p = 0; p < 8; p++) acc[t * 8 + p] = cb[p];
#pragma unroll 2
        for (int c = 0; c < 64; c++) {
            float4 a = *(const float4*)(sAct + c * MT + grp * 4);
            u64 a0 = pack2(a.x), a1 = pack2(a.y), a2 = pack2(a.z), a3 = pack2(a.w);
            const ulonglong2* wp = (const ulonglong2*)(wbase + c * 64 + gb);
            ulonglong2 wA = wp[0], wB = wp[1], wC = wp[2], wD = wp[3];
            u64 wv[8] = {wA.x, wA.y, wB.x, wB.y, wC.x, wC.y, wD.x, wD.y};
#pragma unroll
            for (int p = 0; p < 8; p++) {
                acc[0 * 8 + p] = ffma2(wv[p], a0, acc[0 * 8 + p]);
                acc[1 * 8 + p] = ffma2(wv[p], a1, acc[1 * 8 + p]);
                acc[2 * 8 + p] = ffma2(wv[p], a2, acc[2 * 8 + p]);
                acc[3 * 8 + p] = ffma2(wv[p], a3, acc[3 * 8 + p]);
            }
        }
#pragma unroll
        for (int p = 0; p < 8; p++) {
            float lo, hi;
            unpack2(acc[0 * 8 + p], lo, hi); tmax0 = fmaxf(tmax0, fmaxf(lo, hi));
            unpack2(acc[1 * 8 + p], lo, hi); tmax1 = fmaxf(tmax1, fmaxf(lo, hi));
            unpack2(acc[2 * 8 + p], lo, hi); tmax2 = fmaxf(tmax2, fmaxf(lo, hi));
            unpack2(acc[3 * 8 + p], lo, hi); tmax3 = fmaxf(tmax3, fmaxf(lo, hi));
        }
    }
    __syncthreads();                    // act dead -> alias as max buffer
    sAct[g * MT + grp * 4 + 0] = tmax0;
    sAct[g * MT + grp * 4 + 1] = tmax1;
    sAct[g * MT + grp * 4 + 2] = tmax2;
    sAct[g * MT + grp * 4 + 3] = tmax3;
    __syncthreads();

    // ---- back to thread = token ----
    const int lane = tid & 31;
    const int wg = blockIdx.x * (MT / 32) + (tid >> 5);    // = b*NN + n
    const int b = wg >> 12;
    const int n = wg & (NN - 1);
    const float4 f = ((const float4*)g_feats)[tokBase + tid];

    float gmax = fmaxf(fmaxf(sAct[tid], sAct[MT + tid]),
                       fmaxf(sAct[2 * MT + tid], sAct[3 * MT + tid]));

    // ---- softmax over the 32 neighbors (one warp = one query) ----
    float m = gmax;
#pragma unroll
    for (int off = 16; off; off >>= 1) m = fmaxf(m, __shfl_xor_sync(FULL, m, off));
    float e = __expf(gmax - m);
    float ssum = e;
#pragma unroll
    for (int off = 16; off; off >>= 1) ssum += __shfl_xor_sync(FULL, ssum, off);
    float w = e / ssum;

    // out = q + sum_j w_j * resi_j   (since sum w = 1)
    float wx = w * f.x, wy = w * f.y, wz = w * f.z;
#pragma unroll
    for (int off = 16; off; off >>= 1) {
        wx += __shfl_xor_sync(FULL, wx, off);
        wy += __shfl_xor_sync(FULL, wy, off);
        wz += __shfl_xor_sync(FULL, wz, off);
    }
    if (lane == 0) {
        const float* qb = p1 + b * 3 * NN;
        out[b * 3 * NN + n]          = qb[n]          + wx;
        out[b * 3 * NN + NN + n]     = qb[NN + n]     + wy;
        out[b * 3 * NN + 2 * NN + n] = qb[2 * NN + n] + wz;
    }
}

// ---------------- launch ---------------------------------------------------
extern "C" void kernel_launch(void* const* d_in, const int* in_sizes, int n_in,
                              void* d_out, int out_size)
{
    const float* p1 = (const float*)d_in[0];
    const float* p2 = (const float*)d_in[1];
    // d_in[2] = k (fixed at 16 for this shape)
    const float* w0 = (const float*)d_in[3];
    const float* b0 = (const float*)d_in[4];
    const float* g0 = (const float*)d_in[5];
    const float* e0 = (const float*)d_in[6];
    const float* m0 = (const float*)d_in[7];
    const float* v0 = (const float*)d_in[8];
    const float* w1 = (const float*)d_in[9];
    const float* b1 = (const float*)d_in[10];
    const float* g1 = (const float*)d_in[11];
    const float* e1 = (const float*)d_in[12];
    const float* m1 = (const float*)d_in[13];
    const float* v1 = (const float*)d_in[14];
    const float* w2 = (const float*)d_in[15];
    const float* b2 = (const float*)d_in[16];
    const float* g2 = (const float*)d_in[17];
    const float* e2 = (const float*)d_in[18];
    const float* m2 = (const float*)d_in[19];
    const float* v2 = (const float*)d_in[20];

    cudaFuncSetAttribute(mlp_kernel, cudaFuncAttributeMaxDynamicSharedMemorySize, SMEM_BYTES);
    cudaFuncSetAttribute(knn_kernel, cudaFuncAttributeMaxDynamicSharedMemorySize, NN * 16);

    knn_kernel<<<dim3(NN / 16, BB, 2), 512, NN * 16>>>(p1, p2);

    const int ntok = BB * NN * NB;              // 524288 tokens
    mlp_kernel<<<ntok / MT, MT, SMEM_BYTES>>>(
        p1, (float*)d_out,
        w0, b0, g0, e0, m0, v0,
        w1, b1, g1, e1, m1, v1,
        w2, b2, g2, e2, m2, v2);
}